// round 14
// baseline (speedup 1.0000x reference)
#include <cuda_runtime.h>
#include <cuda_bf16.h>

#define B_  2
#define L_  2048
#define D_  1024
#define H_  16
#define DH_ 64

typedef unsigned long long u64;
typedef unsigned int u32;

// ===================== PTX helpers (base sm_103 ISA only) =====================
__device__ __forceinline__ u32 smem_u32(const void* p) {
    u32 a;
    asm("{ .reg .u64 t; cvta.to.shared.u64 t, %1; cvt.u32.u64 %0, t; }"
        : "=r"(a) : "l"(p));
    return a;
}
__device__ __forceinline__ void ldsm4(u32* r, u32 addr) {
    asm volatile("ldmatrix.sync.aligned.m8n8.x4.shared.b16 {%0,%1,%2,%3},[%4];"
                 : "=r"(r[0]), "=r"(r[1]), "=r"(r[2]), "=r"(r[3]) : "r"(addr));
}
__device__ __forceinline__ void mma16816(float* c, const u32* a, const u32* b) {
    asm volatile(
        "mma.sync.aligned.m16n8k16.row.col.f32.bf16.bf16.f32 "
        "{%0,%1,%2,%3},{%4,%5,%6,%7},{%8,%9},{%0,%1,%2,%3};"
        : "+f"(c[0]), "+f"(c[1]), "+f"(c[2]), "+f"(c[3])
        : "r"(a[0]), "r"(a[1]), "r"(a[2]), "r"(a[3]), "r"(b[0]), "r"(b[1]));
}
__device__ __forceinline__ void cp16(u32 saddr, const void* gaddr) {
    asm volatile("cp.async.cg.shared.global [%0],[%1],16;"
                 :: "r"(saddr), "l"(gaddr));
}
#define CP_COMMIT() asm volatile("cp.async.commit_group;" ::: "memory")
#define CP_WAIT1()  asm volatile("cp.async.wait_group 1;" ::: "memory")
#define CP_WAIT0()  asm volatile("cp.async.wait_group 0;" ::: "memory")

// pack two fp32 -> bf16x2 (upper = a, lower = b)
__device__ __forceinline__ u32 cvt2(float a, float b) {
    u32 r; asm("cvt.rn.bf16x2.f32 %0,%1,%2;" : "=r"(r) : "f"(a), "f"(b));
    return r;
}
__device__ __forceinline__ float lo_f(u32 w) { return __uint_as_float(w << 16); }
__device__ __forceinline__ float hi_f(u32 w) { return __uint_as_float(w & 0xffff0000u); }

// ===================== device scratch =====================
// W/x bf16 splits for the projection GEMM
__device__ unsigned short g_Wh[3072 * 1024];
__device__ unsigned short g_Wl[3072 * 1024];
__device__ unsigned short g_xh[4096 * 1024];
__device__ unsigned short g_xl[4096 * 1024];
// attention operands, bf16 hi/lo:
// Q,K: [bh][l][64]  (d contiguous)   V: [bh][dh][2048] (key contiguous)
__device__ unsigned short g_Qh[32 * 2048 * 64], g_Ql[32 * 2048 * 64];
__device__ unsigned short g_Kh[32 * 2048 * 64], g_Kl[32 * 2048 * 64];
__device__ unsigned short g_Vh[32 * 64 * 2048], g_Vl[32 * 64 * 2048];

// ===================== fused split-prep: fp32 -> bf16 hi + bf16 lo ============
// blocks 0..4095 -> x (1M float4); 4096..7167 -> Wq/Wk/Wv (256K float4 each)
__global__ void split_all_kernel(const float* __restrict__ x,
                                 const float* __restrict__ Wq,
                                 const float* __restrict__ Wk,
                                 const float* __restrict__ Wv)
{
    const int bid = blockIdx.x;
    const float* src;
    unsigned short *dh, *dl;
    int idx;
    if (bid < 4096) {
        src = x; dh = g_xh; dl = g_xl;
        idx = bid * 256 + threadIdx.x;
    } else {
        int wsel = (bid - 4096) >> 10;          // 0,1,2
        int off  = (bid - 4096) & 1023;
        src = (wsel == 0) ? Wq : (wsel == 1) ? Wk : Wv;
        dh = g_Wh + (size_t)wsel * 1048576;
        dl = g_Wl + (size_t)wsel * 1048576;
        idx = off * 256 + threadIdx.x;
    }
    float4 v = ((const float4*)src)[idx];
    float f[4] = {v.x, v.y, v.z, v.w};
    u32 hw[4], lw[4];
#pragma unroll
    for (int k = 0; k < 4; k++) {
        __nv_bfloat16 h = __float2bfloat16(f[k]);
        __nv_bfloat16 l = __float2bfloat16(f[k] - __bfloat162float(h));
        hw[k] = __bfloat16_as_ushort(h);
        lw[k] = __bfloat16_as_ushort(l);
    }
    ((uint2*)dh)[idx] = make_uint2(hw[0] | (hw[1] << 16), hw[2] | (hw[3] << 16));
    ((uint2*)dl)[idx] = make_uint2(lw[0] | (lw[1] << 16), lw[2] | (lw[3] << 16));
}

// ===================== HMMA bf16x3 projection GEMM (unchanged, known-good) ====
#define TSTRIDE 72
#define TILE_B  (128 * TSTRIDE * 2)
#define STAGE_B (4 * TILE_B)
#define MM_SMEM (2 * STAGE_B)

__global__ __launch_bounds__(256, 1) void mm_kernel()
{
    extern __shared__ char dsm[];
    const int tid = threadIdx.x, wid = tid >> 5, lane = tid & 31;
    const int n0  = blockIdx.x * 128;
    const int eg0 = blockIdx.y * 128;
    const int which = eg0 >> 10;      // 0=Q,1=K,2=V
    const int e0 = eg0 & 1023;
    const int b  = n0 >> 11;
    const int l0 = n0 & (L_ - 1);
    const int wm = wid & 1, wn = wid >> 1;

    const u32 smem0 = smem_u32(dsm);
    const unsigned short* gsrc[4] = {
        g_Wh + (size_t)eg0 * 1024, g_Wl + (size_t)eg0 * 1024,
        g_xh + (size_t)n0  * 1024, g_xl + (size_t)n0  * 1024 };

    auto issue = [&](int c, int s) {
        const int kc = c * 64;
        const u32 sb = smem0 + s * STAGE_B;
#pragma unroll
        for (int t = 0; t < 4; t++) {
#pragma unroll
            for (int it = 0; it < 4; it++) {
                int g = tid + it * 256;
                int row = g >> 3, seg = g & 7;
                cp16(sb + t * TILE_B + row * (TSTRIDE * 2) + seg * 16,
                     gsrc[t] + (size_t)row * 1024 + kc + seg * 8);
            }
        }
        CP_COMMIT();
    };

    float acc[4][4][4];
#pragma unroll
    for (int i = 0; i < 4; i++)
#pragma unroll
        for (int j = 0; j < 4; j++)
#pragma unroll
            for (int k = 0; k < 4; k++) acc[i][j][k] = 0.0f;

    issue(0, 0);
    for (int c = 0; c < 16; c++) {
        if (c + 1 < 16) issue(c + 1, (c + 1) & 1);
        if (c + 1 < 16) CP_WAIT1(); else CP_WAIT0();
        __syncthreads();

        const u32 sA  = smem0 + (c & 1) * STAGE_B;
        const u32 sAl = sA + TILE_B;
        const u32 sB  = sA + 2 * TILE_B;
        const u32 sBl = sA + 3 * TILE_B;

        const int arow = 64 * wm + (lane & 15);
        const int brow = 32 * wn + (lane & 15);
        const u32 koffB = ((lane >> 4) & 1) * 16;

#pragma unroll
        for (int ks = 0; ks < 4; ks++) {
            const u32 ko = ks * 32 + koffB;
            u32 Ah[4][4], Al[4][4], Bh[4][2], Bl[4][2];
#pragma unroll
            for (int am = 0; am < 4; am++) {
                u32 ad = (arow + am * 16) * (TSTRIDE * 2) + ko;
                ldsm4(Ah[am], sA  + ad);
                ldsm4(Al[am], sAl + ad);
            }
#pragma unroll
            for (int an2 = 0; an2 < 2; an2++) {
                u32 r[4], ad = (brow + an2 * 16) * (TSTRIDE * 2) + ko;
                ldsm4(r, sB + ad);
                Bh[an2 * 2][0] = r[0]; Bh[an2 * 2 + 1][0] = r[1];
                Bh[an2 * 2][1] = r[2]; Bh[an2 * 2 + 1][1] = r[3];
                ldsm4(r, sBl + ad);
                Bl[an2 * 2][0] = r[0]; Bl[an2 * 2 + 1][0] = r[1];
                Bl[an2 * 2][1] = r[2]; Bl[an2 * 2 + 1][1] = r[3];
            }
#pragma unroll
            for (int am = 0; am < 4; am++)
#pragma unroll
                for (int an = 0; an < 4; an++) {
                    mma16816(acc[am][an], Ah[am], Bh[an]);
                    mma16816(acc[am][an], Ah[am], Bl[an]);
                    mma16816(acc[am][an], Al[am], Bh[an]);
                }
        }
        __syncthreads();
    }

    const int g = lane >> 2, tg = lane & 3;

    if (which == 2) {
        // V: acc orientation (row=feature->dh, col=l->key) matches [dh][key]
#pragma unroll
        for (int am = 0; am < 4; am++)
#pragma unroll
            for (int an = 0; an < 4; an++) {
                int el = e0 + 64 * wm + am * 16 + g;    // +8 stays in same head
                int h = el >> 6, dh = el & 63;
                int col = l0 + 32 * wn + an * 8 + tg * 2;
                size_t base0 = ((size_t)(b * 16 + h) * 64 + dh) * 2048 + col;
                size_t base1 = base0 + (size_t)8 * 2048;
                u32 w0 = cvt2(acc[am][an][1], acc[am][an][0]);
                u32 w1 = cvt2(acc[am][an][3], acc[am][an][2]);
                *(u32*)&g_Vh[base0] = w0;
                *(u32*)&g_Vh[base1] = w1;
                u32 l0w = cvt2(acc[am][an][1] - hi_f(w0), acc[am][an][0] - lo_f(w0));
                u32 l1w = cvt2(acc[am][an][3] - hi_f(w1), acc[am][an][2] - lo_f(w1));
                *(u32*)&g_Vl[base0] = l0w;
                *(u32*)&g_Vl[base1] = l1w;
            }
    } else {
        // Q/K: transpose to [l][e] through fp32 smem, then convert to bf16 hi/lo
        float* stage = (float*)dsm;
#pragma unroll
        for (int am = 0; am < 4; am++)
#pragma unroll
            for (int an = 0; an < 4; an++) {
                int e = 64 * wm + am * 16 + g;
                int l = 32 * wn + an * 8 + tg * 2;
                stage[l * 132 + e]           = acc[am][an][0];
                stage[(l + 1) * 132 + e]     = acc[am][an][1];
                stage[l * 132 + e + 8]       = acc[am][an][2];
                stage[(l + 1) * 132 + e + 8] = acc[am][an][3];
            }
        __syncthreads();
        const int l = tid >> 1, half = tid & 1;
        const int h = (e0 >> 6) + half;
        unsigned short* dsth = ((which == 0) ? g_Qh : g_Kh)
                             + ((size_t)(b * 16 + h) * 2048 + l0 + l) * 64;
        unsigned short* dstl = ((which == 0) ? g_Ql : g_Kl)
                             + ((size_t)(b * 16 + h) * 2048 + l0 + l) * 64;
#pragma unroll
        for (int i = 0; i < 16; i++) {
            float4 v = *(float4*)&stage[l * 132 + half * 64 + i * 4];
            u32 w0 = cvt2(v.y, v.x), w1 = cvt2(v.w, v.z);
            *(uint2*)&dsth[i * 4] = make_uint2(w0, w1);
            u32 r0 = cvt2(v.y - hi_f(w0), v.x - lo_f(w0));
            u32 r1 = cvt2(v.w - hi_f(w1), v.z - lo_f(w1));
            *(uint2*)&dstl[i * 4] = make_uint2(r0, r1);
        }
    }
}

// ===================== HMMA flash attention =====================
// CTA = one bh x 128 q-rows; 8 warps x 16 q-rows; key tiles of 64.
// R14: __launch_bounds__(256,2) — 108KB smem fits 2 CTAs/SM, hiding the
// serial softmax/repack bubbles of one CTA under the other's MMA bursts.
#define AQ_B   18432              // 128 rows * 144B, per hi/lo
#define AKV_B  9216               // 64 rows * 144B
#define ASTG_B (4 * AKV_B)        // Kh,Kl,Vh,Vl
#define ATT_SMEM (2 * AQ_B + 2 * ASTG_B)   // 110592

__global__ __launch_bounds__(256, 2)
void attn_kernel(const int* __restrict__ mask, float* __restrict__ out)
{
    extern __shared__ char dsm[];
    const int tid = threadIdx.x, w = tid >> 5, lane = tid & 31;
    const int qt = 15 - (int)blockIdx.x;       // heavy tiles first
    const int bh = blockIdx.y;
    const int b  = bh >> 4;
    const int h  = bh & 15;
    const int q0 = qt * 128;
    const int bL = b * L_;

    const u32 smem0 = smem_u32(dsm);
    const u32 sQh = smem0, sQl = smem0 + AQ_B;

    const int g  = lane >> 2, tg = lane & 3;
    const int frow = lane & 15;                 // ldmatrix row within 16
    const u32 koff = ((lane >> 4) & 1) * 16;
    const int qbase = q0 + w * 16;
    const int qlo = qbase, qhi = qbase + 15;

    // --- initial loads: Q tile (hi+lo) + first K/V stage, one cp.async group ---
    {
        const unsigned short* gq  = g_Qh + ((size_t)bh * 2048 + q0) * 64;
        const unsigned short* gql = g_Ql + ((size_t)bh * 2048 + q0) * 64;
#pragma unroll
        for (int it = 0; it < 4; it++) {
            int idx = tid + it * 256;           // 1024 segs
            int row = idx >> 3, seg = idx & 7;
            cp16(sQh + row * 144 + seg * 16, gq  + (size_t)row * 64 + seg * 8);
            cp16(sQl + row * 144 + seg * 16, gql + (size_t)row * 64 + seg * 8);
        }
    }
    auto issue = [&](int kt, int s) {
        const int k0 = kt * 64;
        const u32 sb = smem0 + 2 * AQ_B + s * ASTG_B;
#pragma unroll
        for (int it = 0; it < 2; it++) {
            int idx = tid + it * 256;           // 512 segs per sub-tile
            int row = idx >> 3, seg = idx & 7;
            cp16(sb + row * 144 + seg * 16,
                 g_Kh + ((size_t)bh * 2048 + k0 + row) * 64 + seg * 8);
            cp16(sb + AKV_B + row * 144 + seg * 16,
                 g_Kl + ((size_t)bh * 2048 + k0 + row) * 64 + seg * 8);
            cp16(sb + 2 * AKV_B + row * 144 + seg * 16,
                 g_Vh + ((size_t)bh * 64 + row) * 2048 + k0 + seg * 8);
            cp16(sb + 3 * AKV_B + row * 144 + seg * 16,
                 g_Vl + ((size_t)bh * 64 + row) * 2048 + k0 + seg * 8);
        }
    };
    issue(0, 0);
    CP_COMMIT();

    u32 Qh[4][4], Ql[4][4];
    float oacc[8][4];
    float den0 = 0.f, den1 = 0.f;
#pragma unroll
    for (int n = 0; n < 8; n++)
#pragma unroll
        for (int k = 0; k < 4; k++) oacc[n][k] = 0.0f;

    const int nt = 2 * qt + 2;
    for (int kt = 0; kt < nt; kt++) {
        if (kt + 1 < nt) { issue(kt + 1, (kt + 1) & 1); CP_COMMIT(); CP_WAIT1(); }
        else CP_WAIT0();
        __syncthreads();

        if (kt == 0) {                          // hoist Q fragments once
#pragma unroll
            for (int ks = 0; ks < 4; ks++) {
                u32 ad = (u32)(w * 16 + frow) * 144 + ks * 32 + koff;
                ldsm4(Qh[ks], sQh + ad);
                ldsm4(Ql[ks], sQl + ad);
            }
        }

        const int k0 = kt * 64;
        if (k0 <= qhi) {                        // warp-uniform liveness
            const u32 sb = smem0 + 2 * AQ_B + (kt & 1) * ASTG_B;
            const u32 sKh = sb, sKl = sb + AKV_B, sVh = sb + 2 * AKV_B, sVl = sb + 3 * AKV_B;

            // ---- S = Q K^T (bf16x3) ----
            float sacc[8][4];
#pragma unroll
            for (int n = 0; n < 8; n++)
#pragma unroll
                for (int k = 0; k < 4; k++) sacc[n][k] = 0.0f;
#pragma unroll
            for (int ks = 0; ks < 4; ks++) {
#pragma unroll
                for (int an2 = 0; an2 < 4; an2++) {
                    u32 rh[4], rl[4];
                    u32 ad = (frow + an2 * 16) * 144 + ks * 32 + koff;
                    ldsm4(rh, sKh + ad);
                    ldsm4(rl, sKl + ad);
                    u32 b0h[2] = {rh[0], rh[2]}, b1h[2] = {rh[1], rh[3]};
                    u32 b0l[2] = {rl[0], rl[2]}, b1l[2] = {rl[1], rl[3]};
                    mma16816(sacc[an2 * 2],     Qh[ks], b0h);
                    mma16816(sacc[an2 * 2],     Qh[ks], b0l);
                    mma16816(sacc[an2 * 2],     Ql[ks], b0h);
                    mma16816(sacc[an2 * 2 + 1], Qh[ks], b1h);
                    mma16816(sacc[an2 * 2 + 1], Qh[ks], b1l);
                    mma16816(sacc[an2 * 2 + 1], Ql[ks], b1h);
                }
            }

            // ---- softmax (fixed shift tau) ----
            const bool noc = (k0 + 63 <= qlo);  // tile fully below diagonal
            int mw = __ldg(mask + bL + k0 + lane * 2) &
                     __ldg(mask + bL + k0 + lane * 2 + 1);
            const bool fastm = (__ballot_sync(0xffffffffu, mw != 0) == 0xffffffffu);

#pragma unroll
            for (int n = 0; n < 8; n++) {
                float p[4];
#pragma unroll
                for (int k = 0; k < 4; k++) {
                    float t = __expf(sacc[n][k] * 0.25f);          // e^{2 s/8}
                    p[k] = __expf(__fdividef(-60.0f, t + 1.0f));
                }
                const int key = k0 + n * 8 + tg * 2;
                if (!noc) {
                    if (key     > qbase + g)     p[0] = 0.f;
                    if (key + 1 > qbase + g)     p[1] = 0.f;
                    if (key     > qbase + g + 8) p[2] = 0.f;
                    if (key + 1 > qbase + g + 8) p[3] = 0.f;
                }
                if (!fastm) {
                    bool m0 = __ldg(mask + bL + key) != 0;
                    bool m1 = __ldg(mask + bL + key + 1) != 0;
                    if (!m0) { p[0] = 0.f; p[2] = 0.f; }
                    if (!m1) { p[1] = 0.f; p[3] = 0.f; }
                }
                den0 += p[0] + p[1];
                den1 += p[2] + p[3];
                sacc[n][0] = p[0]; sacc[n][1] = p[1];
                sacc[n][2] = p[2]; sacc[n][3] = p[3];
            }

            // ---- O += P V (bf16x3), P packed per k-chunk in registers ----
#pragma unroll
            for (int j = 0; j < 4; j++) {
                u32 Pah[4], Pal[4];
                {
                    float* pA = sacc[2 * j];
                    float* pB = sacc[2 * j + 1];
                    Pah[0] = cvt2(pA[1], pA[0]);
                    Pah[1] = cvt2(pA[3], pA[2]);
                    Pah[2] = cvt2(pB[1], pB[0]);
                    Pah[3] = cvt2(pB[3], pB[2]);
                    Pal[0] = cvt2(pA[1] - hi_f(Pah[0]), pA[0] - lo_f(Pah[0]));
                    Pal[1] = cvt2(pA[3] - hi_f(Pah[1]), pA[2] - lo_f(Pah[1]));
                    Pal[2] = cvt2(pB[1] - hi_f(Pah[2]), pB[0] - lo_f(Pah[2]));
                    Pal[3] = cvt2(pB[3] - hi_f(Pah[3]), pB[2] - lo_f(Pah[3]));
                }
#pragma unroll
                for (int an2 = 0; an2 < 4; an2++) {
                    u32 rh[4], rl[4];
                    u32 ad = (frow + an2 * 16) * 144 + j * 32 + koff;
                    ldsm4(rh, sVh + ad);
                    ldsm4(rl, sVl + ad);
                    u32 b0h[2] = {rh[0], rh[2]}, b1h[2] = {rh[1], rh[3]};
                    u32 b0l[2] = {rl[0], rl[2]}, b1l[2] = {rl[1], rl[3]};
                    mma16816(oacc[an2 * 2],     Pah, b0h);
                    mma16816(oacc[an2 * 2],     Pah, b0l);
                    mma16816(oacc[an2 * 2],     Pal, b0h);
                    mma16816(oacc[an2 * 2 + 1], Pah, b1h);
                    mma16816(oacc[an2 * 2 + 1], Pah, b1l);
                    mma16816(oacc[an2 * 2 + 1], Pal, b1h);
                }
            }
        }
        __syncthreads();                        // stage reusable
    }

    // ---- row-sum reduce across tg group (lanes xor 1,2) ----
    den0 += __shfl_xor_sync(0xffffffffu, den0, 1);
    den0 += __shfl_xor_sync(0xffffffffu, den0, 2);
    den1 += __shfl_xor_sync(0xffffffffu, den1, 1);
    den1 += __shfl_xor_sync(0xffffffffu, den1, 2);
    const float iv0 = __frcp_rn(den0), iv1 = __frcp_rn(den1);

    const int row0 = qbase + g;
#pragma unroll
    for (int n = 0; n < 8; n++) {
        const int col = h * 64 + n * 8 + tg * 2;
        *(float2*)&out[(size_t)(bL + row0) * 1024 + col] =
            make_float2(oacc[n][0] * iv0, oacc[n][1] * iv0);
        *(float2*)&out[(size_t)(bL + row0 + 8) * 1024 + col] =
            make_float2(oacc[n][2] * iv1, oacc[n][3] * iv1);
    }
}

// ---------------------------------------------------------------------------
extern "C" void kernel_launch(void* const* d_in, const int* in_sizes, int n_in,
                              void* d_out, int out_size)
{
    const float* x    = (const float*)d_in[0];
    const int*   mask = (const int*)  d_in[1];
    const float* Wq   = (const float*)d_in[2];
    const float* Wk   = (const float*)d_in[3];
    const float* Wv   = (const float*)d_in[4];
    float* out = (float*)d_out;

    static int attr_set = 0;
    if (!attr_set) {
        cudaFuncSetAttribute(mm_kernel,
                             cudaFuncAttributeMaxDynamicSharedMemorySize, MM_SMEM);
        cudaFuncSetAttribute(attn_kernel,
                             cudaFuncAttributeMaxDynamicSharedMemorySize, ATT_SMEM);
        attr_set = 1;
    }

    split_all_kernel<<<7168, 256>>>(x, Wq, Wk, Wv);
    mm_kernel<<<dim3(32, 24), 256, MM_SMEM>>>();
    attn_kernel<<<dim3(16, 32), 256, ATT_SMEM>>>(mask, out);
}

// round 15
// speedup vs baseline: 1.0337x; 1.0337x over previous
#include <cuda_runtime.h>
#include <cuda_bf16.h>

#define B_  2
#define L_  2048
#define D_  1024
#define H_  16
#define DH_ 64

typedef unsigned long long u64;
typedef unsigned int u32;

// ===================== PTX helpers (base sm_103 ISA only) =====================
__device__ __forceinline__ u32 smem_u32(const void* p) {
    u32 a;
    asm("{ .reg .u64 t; cvta.to.shared.u64 t, %1; cvt.u32.u64 %0, t; }"
        : "=r"(a) : "l"(p));
    return a;
}
__device__ __forceinline__ void ldsm4(u32* r, u32 addr) {
    asm volatile("ldmatrix.sync.aligned.m8n8.x4.shared.b16 {%0,%1,%2,%3},[%4];"
                 : "=r"(r[0]), "=r"(r[1]), "=r"(r[2]), "=r"(r[3]) : "r"(addr));
}
__device__ __forceinline__ void mma16816(float* c, const u32* a, const u32* b) {
    asm volatile(
        "mma.sync.aligned.m16n8k16.row.col.f32.bf16.bf16.f32 "
        "{%0,%1,%2,%3},{%4,%5,%6,%7},{%8,%9},{%0,%1,%2,%3};"
        : "+f"(c[0]), "+f"(c[1]), "+f"(c[2]), "+f"(c[3])
        : "r"(a[0]), "r"(a[1]), "r"(a[2]), "r"(a[3]), "r"(b[0]), "r"(b[1]));
}
__device__ __forceinline__ void cp16(u32 saddr, const void* gaddr) {
    asm volatile("cp.async.cg.shared.global [%0],[%1],16;"
                 :: "r"(saddr), "l"(gaddr));
}
#define CP_COMMIT() asm volatile("cp.async.commit_group;" ::: "memory")
#define CP_WAIT1()  asm volatile("cp.async.wait_group 1;" ::: "memory")
#define CP_WAIT0()  asm volatile("cp.async.wait_group 0;" ::: "memory")

// pack two fp32 -> bf16x2 (upper = a, lower = b)
__device__ __forceinline__ u32 cvt2(float a, float b) {
    u32 r; asm("cvt.rn.bf16x2.f32 %0,%1,%2;" : "=r"(r) : "f"(a), "f"(b));
    return r;
}
__device__ __forceinline__ float lo_f(u32 w) { return __uint_as_float(w << 16); }
__device__ __forceinline__ float hi_f(u32 w) { return __uint_as_float(w & 0xffff0000u); }

// ===================== device scratch =====================
// W/x bf16 splits for the projection GEMM
__device__ unsigned short g_Wh[3072 * 1024];
__device__ unsigned short g_Wl[3072 * 1024];
__device__ unsigned short g_xh[4096 * 1024];
__device__ unsigned short g_xl[4096 * 1024];
// attention operands, bf16 hi/lo:
// Q,K: [bh][l][64]  (d contiguous)   V: [bh][dh][2048] (key contiguous)
__device__ unsigned short g_Qh[32 * 2048 * 64], g_Ql[32 * 2048 * 64];
__device__ unsigned short g_Kh[32 * 2048 * 64], g_Kl[32 * 2048 * 64];
__device__ unsigned short g_Vh[32 * 64 * 2048], g_Vl[32 * 64 * 2048];

// ===================== fused split-prep: fp32 -> bf16 hi + bf16 lo ============
// blocks 0..4095 -> x (1M float4); 4096..7167 -> Wq/Wk/Wv (256K float4 each)
__global__ void split_all_kernel(const float* __restrict__ x,
                                 const float* __restrict__ Wq,
                                 const float* __restrict__ Wk,
                                 const float* __restrict__ Wv)
{
    const int bid = blockIdx.x;
    const float* src;
    unsigned short *dh, *dl;
    int idx;
    if (bid < 4096) {
        src = x; dh = g_xh; dl = g_xl;
        idx = bid * 256 + threadIdx.x;
    } else {
        int wsel = (bid - 4096) >> 10;          // 0,1,2
        int off  = (bid - 4096) & 1023;
        src = (wsel == 0) ? Wq : (wsel == 1) ? Wk : Wv;
        dh = g_Wh + (size_t)wsel * 1048576;
        dl = g_Wl + (size_t)wsel * 1048576;
        idx = off * 256 + threadIdx.x;
    }
    float4 v = ((const float4*)src)[idx];
    float f[4] = {v.x, v.y, v.z, v.w};
    u32 hw[4], lw[4];
#pragma unroll
    for (int k = 0; k < 4; k++) {
        __nv_bfloat16 h = __float2bfloat16(f[k]);
        __nv_bfloat16 l = __float2bfloat16(f[k] - __bfloat162float(h));
        hw[k] = __bfloat16_as_ushort(h);
        lw[k] = __bfloat16_as_ushort(l);
    }
    ((uint2*)dh)[idx] = make_uint2(hw[0] | (hw[1] << 16), hw[2] | (hw[3] << 16));
    ((uint2*)dl)[idx] = make_uint2(lw[0] | (lw[1] << 16), lw[2] | (lw[3] << 16));
}

// ===================== HMMA bf16x3 projection GEMM (unchanged, known-good) ====
#define TSTRIDE 72
#define TILE_B  (128 * TSTRIDE * 2)
#define STAGE_B (4 * TILE_B)
#define MM_SMEM (2 * STAGE_B)

__global__ __launch_bounds__(256, 1) void mm_kernel()
{
    extern __shared__ char dsm[];
    const int tid = threadIdx.x, wid = tid >> 5, lane = tid & 31;
    const int n0  = blockIdx.x * 128;
    const int eg0 = blockIdx.y * 128;
    const int which = eg0 >> 10;      // 0=Q,1=K,2=V
    const int e0 = eg0 & 1023;
    const int b  = n0 >> 11;
    const int l0 = n0 & (L_ - 1);
    const int wm = wid & 1, wn = wid >> 1;

    const u32 smem0 = smem_u32(dsm);
    const unsigned short* gsrc[4] = {
        g_Wh + (size_t)eg0 * 1024, g_Wl + (size_t)eg0 * 1024,
        g_xh + (size_t)n0  * 1024, g_xl + (size_t)n0  * 1024 };

    auto issue = [&](int c, int s) {
        const int kc = c * 64;
        const u32 sb = smem0 + s * STAGE_B;
#pragma unroll
        for (int t = 0; t < 4; t++) {
#pragma unroll
            for (int it = 0; it < 4; it++) {
                int g = tid + it * 256;
                int row = g >> 3, seg = g & 7;
                cp16(sb + t * TILE_B + row * (TSTRIDE * 2) + seg * 16,
                     gsrc[t] + (size_t)row * 1024 + kc + seg * 8);
            }
        }
        CP_COMMIT();
    };

    float acc[4][4][4];
#pragma unroll
    for (int i = 0; i < 4; i++)
#pragma unroll
        for (int j = 0; j < 4; j++)
#pragma unroll
            for (int k = 0; k < 4; k++) acc[i][j][k] = 0.0f;

    issue(0, 0);
    for (int c = 0; c < 16; c++) {
        if (c + 1 < 16) issue(c + 1, (c + 1) & 1);
        if (c + 1 < 16) CP_WAIT1(); else CP_WAIT0();
        __syncthreads();

        const u32 sA  = smem0 + (c & 1) * STAGE_B;
        const u32 sAl = sA + TILE_B;
        const u32 sB  = sA + 2 * TILE_B;
        const u32 sBl = sA + 3 * TILE_B;

        const int arow = 64 * wm + (lane & 15);
        const int brow = 32 * wn + (lane & 15);
        const u32 koffB = ((lane >> 4) & 1) * 16;

#pragma unroll
        for (int ks = 0; ks < 4; ks++) {
            const u32 ko = ks * 32 + koffB;
            u32 Ah[4][4], Al[4][4], Bh[4][2], Bl[4][2];
#pragma unroll
            for (int am = 0; am < 4; am++) {
                u32 ad = (arow + am * 16) * (TSTRIDE * 2) + ko;
                ldsm4(Ah[am], sA  + ad);
                ldsm4(Al[am], sAl + ad);
            }
#pragma unroll
            for (int an2 = 0; an2 < 2; an2++) {
                u32 r[4], ad = (brow + an2 * 16) * (TSTRIDE * 2) + ko;
                ldsm4(r, sB + ad);
                Bh[an2 * 2][0] = r[0]; Bh[an2 * 2 + 1][0] = r[1];
                Bh[an2 * 2][1] = r[2]; Bh[an2 * 2 + 1][1] = r[3];
                ldsm4(r, sBl + ad);
                Bl[an2 * 2][0] = r[0]; Bl[an2 * 2 + 1][0] = r[1];
                Bl[an2 * 2][1] = r[2]; Bl[an2 * 2 + 1][1] = r[3];
            }
#pragma unroll
            for (int am = 0; am < 4; am++)
#pragma unroll
                for (int an = 0; an < 4; an++) {
                    mma16816(acc[am][an], Ah[am], Bh[an]);
                    mma16816(acc[am][an], Ah[am], Bl[an]);
                    mma16816(acc[am][an], Al[am], Bh[an]);
                }
        }
        __syncthreads();
    }

    const int g = lane >> 2, tg = lane & 3;

    if (which == 2) {
        // V: acc orientation (row=feature->dh, col=l->key) matches [dh][key]
#pragma unroll
        for (int am = 0; am < 4; am++)
#pragma unroll
            for (int an = 0; an < 4; an++) {
                int el = e0 + 64 * wm + am * 16 + g;    // +8 stays in same head
                int h = el >> 6, dh = el & 63;
                int col = l0 + 32 * wn + an * 8 + tg * 2;
                size_t base0 = ((size_t)(b * 16 + h) * 64 + dh) * 2048 + col;
                size_t base1 = base0 + (size_t)8 * 2048;
                u32 w0 = cvt2(acc[am][an][1], acc[am][an][0]);
                u32 w1 = cvt2(acc[am][an][3], acc[am][an][2]);
                *(u32*)&g_Vh[base0] = w0;
                *(u32*)&g_Vh[base1] = w1;
                u32 l0w = cvt2(acc[am][an][1] - hi_f(w0), acc[am][an][0] - lo_f(w0));
                u32 l1w = cvt2(acc[am][an][3] - hi_f(w1), acc[am][an][2] - lo_f(w1));
                *(u32*)&g_Vl[base0] = l0w;
                *(u32*)&g_Vl[base1] = l1w;
            }
    } else {
        // Q/K: transpose to [l][e] through fp32 smem, then convert to bf16 hi/lo
        float* stage = (float*)dsm;
#pragma unroll
        for (int am = 0; am < 4; am++)
#pragma unroll
            for (int an = 0; an < 4; an++) {
                int e = 64 * wm + am * 16 + g;
                int l = 32 * wn + an * 8 + tg * 2;
                stage[l * 132 + e]           = acc[am][an][0];
                stage[(l + 1) * 132 + e]     = acc[am][an][1];
                stage[l * 132 + e + 8]       = acc[am][an][2];
                stage[(l + 1) * 132 + e + 8] = acc[am][an][3];
            }
        __syncthreads();
        const int l = tid >> 1, half = tid & 1;
        const int h = (e0 >> 6) + half;
        unsigned short* dsth = ((which == 0) ? g_Qh : g_Kh)
                             + ((size_t)(b * 16 + h) * 2048 + l0 + l) * 64;
        unsigned short* dstl = ((which == 0) ? g_Ql : g_Kl)
                             + ((size_t)(b * 16 + h) * 2048 + l0 + l) * 64;
#pragma unroll
        for (int i = 0; i < 16; i++) {
            float4 v = *(float4*)&stage[l * 132 + half * 64 + i * 4];
            u32 w0 = cvt2(v.y, v.x), w1 = cvt2(v.w, v.z);
            *(uint2*)&dsth[i * 4] = make_uint2(w0, w1);
            u32 r0 = cvt2(v.y - hi_f(w0), v.x - lo_f(w0));
            u32 r1 = cvt2(v.w - hi_f(w1), v.z - lo_f(w1));
            *(uint2*)&dstl[i * 4] = make_uint2(r0, r1);
        }
    }
}

// ===================== HMMA flash attention =====================
// CTA = one bh x 128 q-rows; 8 warps x 16 q-rows; key tiles of 64.
// R15: fused per-16-key-chunk dataflow — QK(j) -> softmax(j) -> PV(j) —
// identical arithmetic order (bit-identical result), smaller live ranges,
// and chunk j+1's MMAs are independent of chunk j's MUFU chain.
// launch_bounds back to (256,1): the (256,2) reg cap caused spills (R14).
#define AQ_B   18432              // 128 rows * 144B, per hi/lo
#define AKV_B  9216               // 64 rows * 144B
#define ASTG_B (4 * AKV_B)        // Kh,Kl,Vh,Vl
#define ATT_SMEM (2 * AQ_B + 2 * ASTG_B)   // 110592

__global__ __launch_bounds__(256, 1)
void attn_kernel(const int* __restrict__ mask, float* __restrict__ out)
{
    extern __shared__ char dsm[];
    const int tid = threadIdx.x, w = tid >> 5, lane = tid & 31;
    const int qt = 15 - (int)blockIdx.x;       // heavy tiles first
    const int bh = blockIdx.y;
    const int b  = bh >> 4;
    const int h  = bh & 15;
    const int q0 = qt * 128;
    const int bL = b * L_;

    const u32 smem0 = smem_u32(dsm);
    const u32 sQh = smem0, sQl = smem0 + AQ_B;

    const int g  = lane >> 2, tg = lane & 3;
    const int frow = lane & 15;                 // ldmatrix row within 16
    const u32 koff = ((lane >> 4) & 1) * 16;
    const int qbase = q0 + w * 16;
    const int qlo = qbase, qhi = qbase + 15;

    // --- initial loads: Q tile (hi+lo) + first K/V stage, one cp.async group ---
    {
        const unsigned short* gq  = g_Qh + ((size_t)bh * 2048 + q0) * 64;
        const unsigned short* gql = g_Ql + ((size_t)bh * 2048 + q0) * 64;
#pragma unroll
        for (int it = 0; it < 4; it++) {
            int idx = tid + it * 256;           // 1024 segs
            int row = idx >> 3, seg = idx & 7;
            cp16(sQh + row * 144 + seg * 16, gq  + (size_t)row * 64 + seg * 8);
            cp16(sQl + row * 144 + seg * 16, gql + (size_t)row * 64 + seg * 8);
        }
    }
    auto issue = [&](int kt, int s) {
        const int k0 = kt * 64;
        const u32 sb = smem0 + 2 * AQ_B + s * ASTG_B;
#pragma unroll
        for (int it = 0; it < 2; it++) {
            int idx = tid + it * 256;           // 512 segs per sub-tile
            int row = idx >> 3, seg = idx & 7;
            cp16(sb + row * 144 + seg * 16,
                 g_Kh + ((size_t)bh * 2048 + k0 + row) * 64 + seg * 8);
            cp16(sb + AKV_B + row * 144 + seg * 16,
                 g_Kl + ((size_t)bh * 2048 + k0 + row) * 64 + seg * 8);
            cp16(sb + 2 * AKV_B + row * 144 + seg * 16,
                 g_Vh + ((size_t)bh * 64 + row) * 2048 + k0 + seg * 8);
            cp16(sb + 3 * AKV_B + row * 144 + seg * 16,
                 g_Vl + ((size_t)bh * 64 + row) * 2048 + k0 + seg * 8);
        }
    };
    issue(0, 0);
    CP_COMMIT();

    u32 Qh[4][4], Ql[4][4];
    float oacc[8][4];
    float den0 = 0.f, den1 = 0.f;
#pragma unroll
    for (int n = 0; n < 8; n++)
#pragma unroll
        for (int k = 0; k < 4; k++) oacc[n][k] = 0.0f;

    const int nt = 2 * qt + 2;
    for (int kt = 0; kt < nt; kt++) {
        if (kt + 1 < nt) { issue(kt + 1, (kt + 1) & 1); CP_COMMIT(); CP_WAIT1(); }
        else CP_WAIT0();
        __syncthreads();

        if (kt == 0) {                          // hoist Q fragments once
#pragma unroll
            for (int ks = 0; ks < 4; ks++) {
                u32 ad = (u32)(w * 16 + frow) * 144 + ks * 32 + koff;
                ldsm4(Qh[ks], sQh + ad);
                ldsm4(Ql[ks], sQl + ad);
            }
        }

        const int k0 = kt * 64;
        if (k0 <= qhi) {                        // warp-uniform liveness
            const u32 sb = smem0 + 2 * AQ_B + (kt & 1) * ASTG_B;
            const u32 sKh = sb, sKl = sb + AKV_B, sVh = sb + 2 * AKV_B, sVl = sb + 3 * AKV_B;

            const bool noc = (k0 + 63 <= qlo);  // tile fully below diagonal
            int mw = __ldg(mask + bL + k0 + lane * 2) &
                     __ldg(mask + bL + k0 + lane * 2 + 1);
            const bool fastm = (__ballot_sync(0xffffffffu, mw != 0) == 0xffffffffu);

            // ---- fused per-16-key-chunk: QK(j) -> softmax(j) -> PV(j) ----
#pragma unroll
            for (int j = 0; j < 4; j++) {
                // S for keys [k0+16j, k0+16j+16)
                float s0[4] = {0.f, 0.f, 0.f, 0.f};
                float s1[4] = {0.f, 0.f, 0.f, 0.f};
#pragma unroll
                for (int ks = 0; ks < 4; ks++) {
                    u32 rh[4], rl[4];
                    u32 ad = (frow + j * 16) * 144 + ks * 32 + koff;
                    ldsm4(rh, sKh + ad);
                    ldsm4(rl, sKl + ad);
                    u32 b0h[2] = {rh[0], rh[2]}, b1h[2] = {rh[1], rh[3]};
                    u32 b0l[2] = {rl[0], rl[2]}, b1l[2] = {rl[1], rl[3]};
                    mma16816(s0, Qh[ks], b0h);
                    mma16816(s0, Qh[ks], b0l);
                    mma16816(s0, Ql[ks], b0h);
                    mma16816(s1, Qh[ks], b1h);
                    mma16816(s1, Qh[ks], b1l);
                    mma16816(s1, Ql[ks], b1h);
                }

                // softmax (fixed shift tau): n = 2j (s0), n = 2j+1 (s1)
                float p0[4], p1[4];
#pragma unroll
                for (int k = 0; k < 4; k++) {
                    float t0 = __expf(s0[k] * 0.25f);
                    p0[k] = __expf(__fdividef(-60.0f, t0 + 1.0f));
                    float t1 = __expf(s1[k] * 0.25f);
                    p1[k] = __expf(__fdividef(-60.0f, t1 + 1.0f));
                }
                const int key0 = k0 + (2 * j) * 8 + tg * 2;
                const int key1 = key0 + 8;
                if (!noc) {
                    if (key0     > qbase + g)     p0[0] = 0.f;
                    if (key0 + 1 > qbase + g)     p0[1] = 0.f;
                    if (key0     > qbase + g + 8) p0[2] = 0.f;
                    if (key0 + 1 > qbase + g + 8) p0[3] = 0.f;
                    if (key1     > qbase + g)     p1[0] = 0.f;
                    if (key1 + 1 > qbase + g)     p1[1] = 0.f;
                    if (key1     > qbase + g + 8) p1[2] = 0.f;
                    if (key1 + 1 > qbase + g + 8) p1[3] = 0.f;
                }
                if (!fastm) {
                    bool m0 = __ldg(mask + bL + key0) != 0;
                    bool m1 = __ldg(mask + bL + key0 + 1) != 0;
                    if (!m0) { p0[0] = 0.f; p0[2] = 0.f; }
                    if (!m1) { p0[1] = 0.f; p0[3] = 0.f; }
                    bool m2 = __ldg(mask + bL + key1) != 0;
                    bool m3 = __ldg(mask + bL + key1 + 1) != 0;
                    if (!m2) { p1[0] = 0.f; p1[2] = 0.f; }
                    if (!m3) { p1[1] = 0.f; p1[3] = 0.f; }
                }
                den0 += p0[0] + p0[1];
                den1 += p0[2] + p0[3];
                den0 += p1[0] + p1[1];
                den1 += p1[2] + p1[3];

                // pack P chunk j (C-frag -> A-frag)
                u32 Pah[4], Pal[4];
                Pah[0] = cvt2(p0[1], p0[0]);
                Pah[1] = cvt2(p0[3], p0[2]);
                Pah[2] = cvt2(p1[1], p1[0]);
                Pah[3] = cvt2(p1[3], p1[2]);
                Pal[0] = cvt2(p0[1] - hi_f(Pah[0]), p0[0] - lo_f(Pah[0]));
                Pal[1] = cvt2(p0[3] - hi_f(Pah[1]), p0[2] - lo_f(Pah[1]));
                Pal[2] = cvt2(p1[1] - hi_f(Pah[2]), p1[0] - lo_f(Pah[2]));
                Pal[3] = cvt2(p1[3] - hi_f(Pah[3]), p1[2] - lo_f(Pah[3]));

                // O += P(j) V(j)  (bf16x3)
#pragma unroll
                for (int an2 = 0; an2 < 4; an2++) {
                    u32 rh[4], rl[4];
                    u32 ad = (frow + an2 * 16) * 144 + j * 32 + koff;
                    ldsm4(rh, sVh + ad);
                    ldsm4(rl, sVl + ad);
                    u32 b0h[2] = {rh[0], rh[2]}, b1h[2] = {rh[1], rh[3]};
                    u32 b0l[2] = {rl[0], rl[2]}, b1l[2] = {rl[1], rl[3]};
                    mma16816(oacc[an2 * 2],     Pah, b0h);
                    mma16816(oacc[an2 * 2],     Pah, b0l);
                    mma16816(oacc[an2 * 2],     Pal, b0h);
                    mma16816(oacc[an2 * 2 + 1], Pah, b1h);
                    mma16816(oacc[an2 * 2 + 1], Pah, b1l);
                    mma16816(oacc[an2 * 2 + 1], Pal, b1h);
                }
            }
        }
        __syncthreads();                        // stage reusable
    }

    // ---- row-sum reduce across tg group (lanes xor 1,2) ----
    den0 += __shfl_xor_sync(0xffffffffu, den0, 1);
    den0 += __shfl_xor_sync(0xffffffffu, den0, 2);
    den1 += __shfl_xor_sync(0xffffffffu, den1, 1);
    den1 += __shfl_xor_sync(0xffffffffu, den1, 2);
    const float iv0 = __frcp_rn(den0), iv1 = __frcp_rn(den1);

    const int row0 = qbase + g;
#pragma unroll
    for (int n = 0; n < 8; n++) {
        const int col = h * 64 + n * 8 + tg * 2;
        *(float2*)&out[(size_t)(bL + row0) * 1024 + col] =
            make_float2(oacc[n][0] * iv0, oacc[n][1] * iv0);
        *(float2*)&out[(size_t)(bL + row0 + 8) * 1024 + col] =
            make_float2(oacc[n][2] * iv1, oacc[n][3] * iv1);
    }
}

// ---------------------------------------------------------------------------
extern "C" void kernel_launch(void* const* d_in, const int* in_sizes, int n_in,
                              void* d_out, int out_size)
{
    const float* x    = (const float*)d_in[0];
    const int*   mask = (const int*)  d_in[1];
    const float* Wq   = (const float*)d_in[2];
    const float* Wk   = (const float*)d_in[3];
    const float* Wv   = (const float*)d_in[4];
    float* out = (float*)d_out;

    static int attr_set = 0;
    if (!attr_set) {
        cudaFuncSetAttribute(mm_kernel,
                             cudaFuncAttributeMaxDynamicSharedMemorySize, MM_SMEM);
        cudaFuncSetAttribute(attn_kernel,
                             cudaFuncAttributeMaxDynamicSharedMemorySize, ATT_SMEM);
        attr_set = 1;
    }

    split_all_kernel<<<7168, 256>>>(x, Wq, Wk, Wv);
    mm_kernel<<<dim3(32, 24), 256, MM_SMEM>>>();
    attn_kernel<<<dim3(16, 32), 256, ATT_SMEM>>>(mask, out);
}

// round 17
// speedup vs baseline: 1.0411x; 1.0072x over previous
#include <cuda_runtime.h>
#include <cuda_bf16.h>
#include <cuda_fp16.h>

#define B_  2
#define L_  2048
#define D_  1024
#define H_  16
#define DH_ 64

typedef unsigned long long u64;
typedef unsigned int u32;

// ===================== PTX helpers (base sm_103 ISA only) =====================
__device__ __forceinline__ u32 smem_u32(const void* p) {
    u32 a;
    asm("{ .reg .u64 t; cvta.to.shared.u64 t, %1; cvt.u32.u64 %0, t; }"
        : "=r"(a) : "l"(p));
    return a;
}
__device__ __forceinline__ void ldsm4(u32* r, u32 addr) {
    asm volatile("ldmatrix.sync.aligned.m8n8.x4.shared.b16 {%0,%1,%2,%3},[%4];"
                 : "=r"(r[0]), "=r"(r[1]), "=r"(r[2]), "=r"(r[3]) : "r"(addr));
}
__device__ __forceinline__ void mma16816(float* c, const u32* a, const u32* b) {
    asm volatile(
        "mma.sync.aligned.m16n8k16.row.col.f32.bf16.bf16.f32 "
        "{%0,%1,%2,%3},{%4,%5,%6,%7},{%8,%9},{%0,%1,%2,%3};"
        : "+f"(c[0]), "+f"(c[1]), "+f"(c[2]), "+f"(c[3])
        : "r"(a[0]), "r"(a[1]), "r"(a[2]), "r"(a[3]), "r"(b[0]), "r"(b[1]));
}
__device__ __forceinline__ void mma16816h(float* c, const u32* a, const u32* b) {
    asm volatile(
        "mma.sync.aligned.m16n8k16.row.col.f32.f16.f16.f32 "
        "{%0,%1,%2,%3},{%4,%5,%6,%7},{%8,%9},{%0,%1,%2,%3};"
        : "+f"(c[0]), "+f"(c[1]), "+f"(c[2]), "+f"(c[3])
        : "r"(a[0]), "r"(a[1]), "r"(a[2]), "r"(a[3]), "r"(b[0]), "r"(b[1]));
}
__device__ __forceinline__ void cp16(u32 saddr, const void* gaddr) {
    asm volatile("cp.async.cg.shared.global [%0],[%1],16;"
                 :: "r"(saddr), "l"(gaddr));
}
#define CP_COMMIT() asm volatile("cp.async.commit_group;" ::: "memory")
#define CP_WAIT1()  asm volatile("cp.async.wait_group 1;" ::: "memory")
#define CP_WAIT0()  asm volatile("cp.async.wait_group 0;" ::: "memory")

// pack two fp32 -> bf16x2 (first arg = upper half)
__device__ __forceinline__ u32 cvt2(float a, float b) {
    u32 r; asm("cvt.rn.bf16x2.f32 %0,%1,%2;" : "=r"(r) : "f"(a), "f"(b));
    return r;
}
__device__ __forceinline__ float lo_f(u32 w) { return __uint_as_float(w << 16); }
__device__ __forceinline__ float hi_f(u32 w) { return __uint_as_float(w & 0xffff0000u); }
// pack two fp32 -> f16x2 (first arg = upper half)
__device__ __forceinline__ u32 cvt2f(float a, float b) {
    u32 r; asm("cvt.rn.f16x2.f32 %0,%1,%2;" : "=r"(r) : "f"(a), "f"(b));
    return r;
}
__device__ __forceinline__ float h_lo(u32 w) {
    return __half2float(__ushort_as_half((unsigned short)(w & 0xffffu)));
}
__device__ __forceinline__ float h_hi(u32 w) {
    return __half2float(__ushort_as_half((unsigned short)(w >> 16)));
}

// ===================== device scratch =====================
// W/x bf16 splits for the projection GEMM
__device__ unsigned short g_Wh[3072 * 1024];
__device__ unsigned short g_Wl[3072 * 1024];
__device__ unsigned short g_xh[4096 * 1024];
__device__ unsigned short g_xl[4096 * 1024];
// attention operands:
// Q,K bf16 hi/lo: [bh][l][64]  (d contiguous)
// V   fp16 hi/lo: [bh][dh][2048] (key contiguous)
__device__ unsigned short g_Qh[32 * 2048 * 64], g_Ql[32 * 2048 * 64];
__device__ unsigned short g_Kh[32 * 2048 * 64], g_Kl[32 * 2048 * 64];
__device__ unsigned short g_Vh[32 * 64 * 2048], g_Vl[32 * 64 * 2048];

// ===================== fused split-prep: fp32 -> bf16 hi + bf16 lo ============
// blocks 0..4095 -> x (1M float4); 4096..7167 -> Wq/Wk/Wv (256K float4 each)
__global__ void split_all_kernel(const float* __restrict__ x,
                                 const float* __restrict__ Wq,
                                 const float* __restrict__ Wk,
                                 const float* __restrict__ Wv)
{
    const int bid = blockIdx.x;
    const float* src;
    unsigned short *dh, *dl;
    int idx;
    if (bid < 4096) {
        src = x; dh = g_xh; dl = g_xl;
        idx = bid * 256 + threadIdx.x;
    } else {
        int wsel = (bid - 4096) >> 10;          // 0,1,2
        int off  = (bid - 4096) & 1023;
        src = (wsel == 0) ? Wq : (wsel == 1) ? Wk : Wv;
        dh = g_Wh + (size_t)wsel * 1048576;
        dl = g_Wl + (size_t)wsel * 1048576;
        idx = off * 256 + threadIdx.x;
    }
    float4 v = ((const float4*)src)[idx];
    float f[4] = {v.x, v.y, v.z, v.w};
    u32 hw[4], lw[4];
#pragma unroll
    for (int k = 0; k < 4; k++) {
        __nv_bfloat16 h = __float2bfloat16(f[k]);
        __nv_bfloat16 l = __float2bfloat16(f[k] - __bfloat162float(h));
        hw[k] = __bfloat16_as_ushort(h);
        lw[k] = __bfloat16_as_ushort(l);
    }
    ((uint2*)dh)[idx] = make_uint2(hw[0] | (hw[1] << 16), hw[2] | (hw[3] << 16));
    ((uint2*)dl)[idx] = make_uint2(lw[0] | (lw[1] << 16), lw[2] | (lw[3] << 16));
}

// ===================== HMMA bf16x3 projection GEMM ============================
// Only change this round: V epilogue emits fp16 hi/lo (for fp16 PV MMAs).
#define TSTRIDE 72
#define TILE_B  (128 * TSTRIDE * 2)
#define STAGE_B (4 * TILE_B)
#define MM_SMEM (2 * STAGE_B)

__global__ __launch_bounds__(256, 1) void mm_kernel()
{
    extern __shared__ char dsm[];
    const int tid = threadIdx.x, wid = tid >> 5, lane = tid & 31;
    const int n0  = blockIdx.x * 128;
    const int eg0 = blockIdx.y * 128;
    const int which = eg0 >> 10;      // 0=Q,1=K,2=V
    const int e0 = eg0 & 1023;
    const int b  = n0 >> 11;
    const int l0 = n0 & (L_ - 1);
    const int wm = wid & 1, wn = wid >> 1;

    const u32 smem0 = smem_u32(dsm);
    const unsigned short* gsrc[4] = {
        g_Wh + (size_t)eg0 * 1024, g_Wl + (size_t)eg0 * 1024,
        g_xh + (size_t)n0  * 1024, g_xl + (size_t)n0  * 1024 };

    auto issue = [&](int c, int s) {
        const int kc = c * 64;
        const u32 sb = smem0 + s * STAGE_B;
#pragma unroll
        for (int t = 0; t < 4; t++) {
#pragma unroll
            for (int it = 0; it < 4; it++) {
                int g = tid + it * 256;
                int row = g >> 3, seg = g & 7;
                cp16(sb + t * TILE_B + row * (TSTRIDE * 2) + seg * 16,
                     gsrc[t] + (size_t)row * 1024 + kc + seg * 8);
            }
        }
        CP_COMMIT();
    };

    float acc[4][4][4];
#pragma unroll
    for (int i = 0; i < 4; i++)
#pragma unroll
        for (int j = 0; j < 4; j++)
#pragma unroll
            for (int k = 0; k < 4; k++) acc[i][j][k] = 0.0f;

    issue(0, 0);
    for (int c = 0; c < 16; c++) {
        if (c + 1 < 16) issue(c + 1, (c + 1) & 1);
        if (c + 1 < 16) CP_WAIT1(); else CP_WAIT0();
        __syncthreads();

        const u32 sA  = smem0 + (c & 1) * STAGE_B;
        const u32 sAl = sA + TILE_B;
        const u32 sB  = sA + 2 * TILE_B;
        const u32 sBl = sA + 3 * TILE_B;

        const int arow = 64 * wm + (lane & 15);
        const int brow = 32 * wn + (lane & 15);
        const u32 koffB = ((lane >> 4) & 1) * 16;

#pragma unroll
        for (int ks = 0; ks < 4; ks++) {
            const u32 ko = ks * 32 + koffB;
            u32 Ah[4][4], Al[4][4], Bh[4][2], Bl[4][2];
#pragma unroll
            for (int am = 0; am < 4; am++) {
                u32 ad = (arow + am * 16) * (TSTRIDE * 2) + ko;
                ldsm4(Ah[am], sA  + ad);
                ldsm4(Al[am], sAl + ad);
            }
#pragma unroll
            for (int an2 = 0; an2 < 2; an2++) {
                u32 r[4], ad = (brow + an2 * 16) * (TSTRIDE * 2) + ko;
                ldsm4(r, sB + ad);
                Bh[an2 * 2][0] = r[0]; Bh[an2 * 2 + 1][0] = r[1];
                Bh[an2 * 2][1] = r[2]; Bh[an2 * 2 + 1][1] = r[3];
                ldsm4(r, sBl + ad);
                Bl[an2 * 2][0] = r[0]; Bl[an2 * 2 + 1][0] = r[1];
                Bl[an2 * 2][1] = r[2]; Bl[an2 * 2 + 1][1] = r[3];
            }
#pragma unroll
            for (int am = 0; am < 4; am++)
#pragma unroll
                for (int an = 0; an < 4; an++) {
                    mma16816(acc[am][an], Ah[am], Bh[an]);
                    mma16816(acc[am][an], Ah[am], Bl[an]);
                    mma16816(acc[am][an], Al[am], Bh[an]);
                }
        }
        __syncthreads();
    }

    const int g = lane >> 2, tg = lane & 3;

    if (which == 2) {
        // V: fp16 hi + fp16 residual (exact to ~2^-22); layout [dh][key]
#pragma unroll
        for (int am = 0; am < 4; am++)
#pragma unroll
            for (int an = 0; an < 4; an++) {
                int el = e0 + 64 * wm + am * 16 + g;    // +8 stays in same head
                int h = el >> 6, dh = el & 63;
                int col = l0 + 32 * wn + an * 8 + tg * 2;
                size_t base0 = ((size_t)(b * 16 + h) * 64 + dh) * 2048 + col;
                size_t base1 = base0 + (size_t)8 * 2048;
                u32 w0 = cvt2f(acc[am][an][1], acc[am][an][0]);
                u32 w1 = cvt2f(acc[am][an][3], acc[am][an][2]);
                *(u32*)&g_Vh[base0] = w0;
                *(u32*)&g_Vh[base1] = w1;
                u32 l0w = cvt2f(acc[am][an][1] - h_hi(w0), acc[am][an][0] - h_lo(w0));
                u32 l1w = cvt2f(acc[am][an][3] - h_hi(w1), acc[am][an][2] - h_lo(w1));
                *(u32*)&g_Vl[base0] = l0w;
                *(u32*)&g_Vl[base1] = l1w;
            }
    } else {
        // Q/K: transpose to [l][e] through fp32 smem, then convert to bf16 hi/lo
        float* stage = (float*)dsm;
#pragma unroll
        for (int am = 0; am < 4; am++)
#pragma unroll
            for (int an = 0; an < 4; an++) {
                int e = 64 * wm + am * 16 + g;
                int l = 32 * wn + an * 8 + tg * 2;
                stage[l * 132 + e]           = acc[am][an][0];
                stage[(l + 1) * 132 + e]     = acc[am][an][1];
                stage[l * 132 + e + 8]       = acc[am][an][2];
                stage[(l + 1) * 132 + e + 8] = acc[am][an][3];
            }
        __syncthreads();
        const int l = tid >> 1, half = tid & 1;
        const int h = (e0 >> 6) + half;
        unsigned short* dsth = ((which == 0) ? g_Qh : g_Kh)
                             + ((size_t)(b * 16 + h) * 2048 + l0 + l) * 64;
        unsigned short* dstl = ((which == 0) ? g_Ql : g_Kl)
                             + ((size_t)(b * 16 + h) * 2048 + l0 + l) * 64;
#pragma unroll
        for (int i = 0; i < 16; i++) {
            float4 v = *(float4*)&stage[l * 132 + half * 64 + i * 4];
            u32 w0 = cvt2(v.y, v.x), w1 = cvt2(v.w, v.z);
            *(uint2*)&dsth[i * 4] = make_uint2(w0, w1);
            u32 r0 = cvt2(v.y - hi_f(w0), v.x - lo_f(w0));
            u32 r1 = cvt2(v.w - hi_f(w1), v.z - lo_f(w1));
            *(uint2*)&dstl[i * 4] = make_uint2(r0, r1);
        }
    }
}

// ===================== HMMA flash attention =====================
// R16: online row-max softmax -> P in a SINGLE fp16 term (range-safe),
// V as fp16 hi/lo. PV MMAs per tile: 96 -> 64 (tile total 192 -> 160).
// QK^T stays bf16x3 (tanh cap amplifies K quantization x30; fp16 K fails).
#define AQ_B   18432              // 128 rows * 144B, per hi/lo
#define AKV_B  9216               // 64 rows * 144B
#define ASTG_B (4 * AKV_B)        // Kh,Kl,Vh,Vl
#define ATT_SMEM (2 * AQ_B + 2 * ASTG_B)   // 110592

__global__ __launch_bounds__(256, 1)
void attn_kernel(const int* __restrict__ mask, float* __restrict__ out)
{
    extern __shared__ char dsm[];
    const int tid = threadIdx.x, w = tid >> 5, lane = tid & 31;
    const int qt = 15 - (int)blockIdx.x;       // heavy tiles first
    const int bh = blockIdx.y;
    const int b  = bh >> 4;
    const int h  = bh & 15;
    const int q0 = qt * 128;
    const int bL = b * L_;

    const u32 smem0 = smem_u32(dsm);
    const u32 sQh = smem0, sQl = smem0 + AQ_B;

    const int g  = lane >> 2, tg = lane & 3;
    const int frow = lane & 15;                 // ldmatrix row within 16
    const u32 koff = ((lane >> 4) & 1) * 16;
    const int qbase = q0 + w * 16;
    const int qlo = qbase, qhi = qbase + 15;

    // --- initial loads: Q tile (hi+lo) + first K/V stage, one cp.async group ---
    {
        const unsigned short* gq  = g_Qh + ((size_t)bh * 2048 + q0) * 64;
        const unsigned short* gql = g_Ql + ((size_t)bh * 2048 + q0) * 64;
#pragma unroll
        for (int it = 0; it < 4; it++) {
            int idx = tid + it * 256;           // 1024 segs
            int row = idx >> 3, seg = idx & 7;
            cp16(sQh + row * 144 + seg * 16, gq  + (size_t)row * 64 + seg * 8);
            cp16(sQl + row * 144 + seg * 16, gql + (size_t)row * 64 + seg * 8);
        }
    }
    auto issue = [&](int kt, int s) {
        const int k0 = kt * 64;
        const u32 sb = smem0 + 2 * AQ_B + s * ASTG_B;
#pragma unroll
        for (int it = 0; it < 2; it++) {
            int idx = tid + it * 256;           // 512 segs per sub-tile
            int row = idx >> 3, seg = idx & 7;
            cp16(sb + row * 144 + seg * 16,
                 g_Kh + ((size_t)bh * 2048 + k0 + row) * 64 + seg * 8);
            cp16(sb + AKV_B + row * 144 + seg * 16,
                 g_Kl + ((size_t)bh * 2048 + k0 + row) * 64 + seg * 8);
            cp16(sb + 2 * AKV_B + row * 144 + seg * 16,
                 g_Vh + ((size_t)bh * 64 + row) * 2048 + k0 + seg * 8);
            cp16(sb + 3 * AKV_B + row * 144 + seg * 16,
                 g_Vl + ((size_t)bh * 64 + row) * 2048 + k0 + seg * 8);
        }
    };
    issue(0, 0);
    CP_COMMIT();

    u32 Qh[4][4], Ql[4][4];
    float oacc[8][4];
    float den0 = 0.f, den1 = 0.f;
    float m0 = -30.0f, m1 = -30.0f;            // logits = 30*tanh > -30 always
#pragma unroll
    for (int n = 0; n < 8; n++)
#pragma unroll
        for (int k = 0; k < 4; k++) oacc[n][k] = 0.0f;

    const int nt = 2 * qt + 2;
    for (int kt = 0; kt < nt; kt++) {
        if (kt + 1 < nt) { issue(kt + 1, (kt + 1) & 1); CP_COMMIT(); CP_WAIT1(); }
        else CP_WAIT0();
        __syncthreads();

        if (kt == 0) {                          // hoist Q fragments once
#pragma unroll
            for (int ks = 0; ks < 4; ks++) {
                u32 ad = (u32)(w * 16 + frow) * 144 + ks * 32 + koff;
                ldsm4(Qh[ks], sQh + ad);
                ldsm4(Ql[ks], sQl + ad);
            }
        }

        const int k0 = kt * 64;
        if (k0 <= qhi) {                        // warp-uniform liveness
            const u32 sb = smem0 + 2 * AQ_B + (kt & 1) * ASTG_B;
            const u32 sKh = sb, sKl = sb + AKV_B, sVh = sb + 2 * AKV_B, sVl = sb + 3 * AKV_B;

            const bool noc = (k0 + 63 <= qlo);  // tile fully below diagonal
            int mw = __ldg(mask + bL + k0 + lane * 2) &
                     __ldg(mask + bL + k0 + lane * 2 + 1);
            const bool fastm = (__ballot_sync(0xffffffffu, mw != 0) == 0xffffffffu);

            // ---- fused per-16-key-chunk: QK(j) -> softmax(j) -> PV(j) ----
#pragma unroll
            for (int j = 0; j < 4; j++) {
                // S for keys [k0+16j, k0+16j+16)
                float s0[4] = {0.f, 0.f, 0.f, 0.f};
                float s1[4] = {0.f, 0.f, 0.f, 0.f};
#pragma unroll
                for (int ks = 0; ks < 4; ks++) {
                    u32 rh[4], rl[4];
                    u32 ad = (frow + j * 16) * 144 + ks * 32 + koff;
                    ldsm4(rh, sKh + ad);
                    ldsm4(rl, sKl + ad);
                    u32 b0h[2] = {rh[0], rh[2]}, b1h[2] = {rh[1], rh[3]};
                    u32 b0l[2] = {rl[0], rl[2]}, b1l[2] = {rl[1], rl[3]};
                    mma16816(s0, Qh[ks], b0h);
                    mma16816(s0, Qh[ks], b0l);
                    mma16816(s0, Ql[ks], b0h);
                    mma16816(s1, Qh[ks], b1h);
                    mma16816(s1, Qh[ks], b1l);
                    mma16816(s1, Ql[ks], b1h);
                }

                // logits = 30*tanh(s/8) = 30 - 60/(e^{s/4}+1)
                float lg0[4], lg1[4];
#pragma unroll
                for (int k = 0; k < 4; k++) {
                    float t0 = __expf(s0[k] * 0.25f);
                    lg0[k] = 30.0f - __fdividef(60.0f, t0 + 1.0f);
                    float t1 = __expf(s1[k] * 0.25f);
                    lg1[k] = 30.0f - __fdividef(60.0f, t1 + 1.0f);
                }
                const int key0 = k0 + (2 * j) * 8 + tg * 2;
                const int key1 = key0 + 8;
                if (!noc) {
                    if (key0     > qbase + g)     lg0[0] = -1e30f;
                    if (key0 + 1 > qbase + g)     lg0[1] = -1e30f;
                    if (key0     > qbase + g + 8) lg0[2] = -1e30f;
                    if (key0 + 1 > qbase + g + 8) lg0[3] = -1e30f;
                    if (key1     > qbase + g)     lg1[0] = -1e30f;
                    if (key1 + 1 > qbase + g)     lg1[1] = -1e30f;
                    if (key1     > qbase + g + 8) lg1[2] = -1e30f;
                    if (key1 + 1 > qbase + g + 8) lg1[3] = -1e30f;
                }
                if (!fastm) {
                    bool ma = __ldg(mask + bL + key0) != 0;
                    bool mb = __ldg(mask + bL + key0 + 1) != 0;
                    if (!ma) { lg0[0] = -1e30f; lg0[2] = -1e30f; }
                    if (!mb) { lg0[1] = -1e30f; lg0[3] = -1e30f; }
                    bool mc = __ldg(mask + bL + key1) != 0;
                    bool md = __ldg(mask + bL + key1 + 1) != 0;
                    if (!mc) { lg1[0] = -1e30f; lg1[2] = -1e30f; }
                    if (!md) { lg1[1] = -1e30f; lg1[3] = -1e30f; }
                }

                // online row max (row g -> m0, row g+8 -> m1); tg-group shfl
                float cm0 = fmaxf(fmaxf(lg0[0], lg0[1]), fmaxf(lg1[0], lg1[1]));
                float cm1 = fmaxf(fmaxf(lg0[2], lg0[3]), fmaxf(lg1[2], lg1[3]));
                cm0 = fmaxf(cm0, __shfl_xor_sync(0xffffffffu, cm0, 1));
                cm0 = fmaxf(cm0, __shfl_xor_sync(0xffffffffu, cm0, 2));
                cm1 = fmaxf(cm1, __shfl_xor_sync(0xffffffffu, cm1, 1));
                cm1 = fmaxf(cm1, __shfl_xor_sync(0xffffffffu, cm1, 2));
                float m0n = fmaxf(m0, cm0), m1n = fmaxf(m1, cm1);
                float sc0 = __expf(m0 - m0n), sc1 = __expf(m1 - m1n);
                m0 = m0n; m1 = m1n;

                float p0[4], p1[4];
                p0[0] = __expf(lg0[0] - m0n);  p0[1] = __expf(lg0[1] - m0n);
                p0[2] = __expf(lg0[2] - m1n);  p0[3] = __expf(lg0[3] - m1n);
                p1[0] = __expf(lg1[0] - m0n);  p1[1] = __expf(lg1[1] - m0n);
                p1[2] = __expf(lg1[2] - m1n);  p1[3] = __expf(lg1[3] - m1n);

                den0 = den0 * sc0 + (p0[0] + p0[1] + p1[0] + p1[1]);
                den1 = den1 * sc1 + (p0[2] + p0[3] + p1[2] + p1[3]);
#pragma unroll
                for (int n = 0; n < 8; n++) {
                    oacc[n][0] *= sc0; oacc[n][1] *= sc0;
                    oacc[n][2] *= sc1; oacc[n][3] *= sc1;
                }

                // pack P chunk j as fp16 A-fragment (single term; p in (0,1])
                u32 Pa[4];
                Pa[0] = cvt2f(p0[1], p0[0]);
                Pa[1] = cvt2f(p0[3], p0[2]);
                Pa[2] = cvt2f(p1[1], p1[0]);
                Pa[3] = cvt2f(p1[3], p1[2]);

                // O += P(j) V(j): fp16 x fp16 (V hi+lo), 4 MMAs per an2
#pragma unroll
                for (int an2 = 0; an2 < 4; an2++) {
                    u32 rh[4], rl[4];
                    u32 ad = (frow + an2 * 16) * 144 + j * 32 + koff;
                    ldsm4(rh, sVh + ad);
                    ldsm4(rl, sVl + ad);
                    u32 b0h[2] = {rh[0], rh[2]}, b1h[2] = {rh[1], rh[3]};
                    u32 b0l[2] = {rl[0], rl[2]}, b1l[2] = {rl[1], rl[3]};
                    mma16816h(oacc[an2 * 2],     Pa, b0h);
                    mma16816h(oacc[an2 * 2],     Pa, b0l);
                    mma16816h(oacc[an2 * 2 + 1], Pa, b1h);
                    mma16816h(oacc[an2 * 2 + 1], Pa, b1l);
                }
            }
        }
        __syncthreads();                        // stage reusable
    }

    // ---- row-sum reduce across tg group (lanes xor 1,2) ----
    den0 += __shfl_xor_sync(0xffffffffu, den0, 1);
    den0 += __shfl_xor_sync(0xffffffffu, den0, 2);
    den1 += __shfl_xor_sync(0xffffffffu, den1, 1);
    den1 += __shfl_xor_sync(0xffffffffu, den1, 2);
    const float iv0 = __frcp_rn(den0), iv1 = __frcp_rn(den1);

    const int row0 = qbase + g;
#pragma unroll
    for (int n = 0; n < 8; n++) {
        const int col = h * 64 + n * 8 + tg * 2;
        *(float2*)&out[(size_t)(bL + row0) * 1024 + col] =
            make_float2(oacc[n][0] * iv0, oacc[n][1] * iv0);
        *(float2*)&out[(size_t)(bL + row0 + 8) * 1024 + col] =
            make_float2(oacc[n][2] * iv1, oacc[n][3] * iv1);
    }
}

// ---------------------------------------------------------------------------
extern "C" void kernel_launch(void* const* d_in, const int* in_sizes, int n_in,
                              void* d_out, int out_size)
{
    const float* x    = (const float*)d_in[0];
    const int*   mask = (const int*)  d_in[1];
    const float* Wq   = (const float*)d_in[2];
    const float* Wk   = (const float*)d_in[3];
    const float* Wv   = (const float*)d_in[4];
    float* out = (float*)d_out;

    static int attr_set = 0;
    if (!attr_set) {
        cudaFuncSetAttribute(mm_kernel,
                             cudaFuncAttributeMaxDynamicSharedMemorySize, MM_SMEM);
        cudaFuncSetAttribute(attn_kernel,
                             cudaFuncAttributeMaxDynamicSharedMemorySize, ATT_SMEM);
        attr_set = 1;
    }

    split_all_kernel<<<7168, 256>>>(x, Wq, Wk, Wv);
    mm_kernel<<<dim3(32, 24), 256, MM_SMEM>>>();
    attn_kernel<<<dim3(16, 32), 256, ATT_SMEM>>>(mask, out);
}